// round 13
// baseline (speedup 1.0000x reference)
#include <cuda_runtime.h>
#include <cuda_fp16.h>
#include <cstdint>

// ============================================================================
// Int8Linear: y[M,N] = (x[M,K] @ W^T[K,N]) * scale[n], fp32 accum
// M=4096, K=4096, N=11008.  compute_103 feature set (mma.sync + cp.async).
// R13 = R12 (session best: 898.1us) + peeled final K-iteration to remove the
// per-iter wait_group-selection branch. All other bytes identical.
// Plateau evidence: regfile 100% (65024/65536), L1 ~61% co-bound, three
// restructure attempts (R7/R8/R11) all regressed.
// ============================================================================

#define BM 128
#define BN 128
#define BK 64
#define STAGES 3
#define THREADS 256

#define STAGE_BYTES 32768  // A 16KB + B 16KB
#define SMEM_TOTAL (STAGES * STAGE_BYTES)  // 96 KB

#define N_MAX 11008
#define K_FIXED 4096
#define M_MAX 4096

__device__ __half g_wh[(size_t)N_MAX * K_FIXED];
__device__ __half g_xh[(size_t)M_MAX * K_FIXED];

// ---------------------------------------------------------------------------
// Fused conversion: blocks [0, wblocks) do W int32->f16 (exact, |w|<=127);
// blocks [wblocks, ...) do x f32->f16 (exact: values originally f16).
// ---------------------------------------------------------------------------
__global__ void convert_fused_kernel(const int* __restrict__ w,
                                     const float* __restrict__ x,
                                     __half* __restrict__ wh,
                                     __half* __restrict__ xh, int nw8,
                                     int wblocks) {
    if ((int)blockIdx.x < wblocks) {
        int i = blockIdx.x * blockDim.x + threadIdx.x;
        if (i >= nw8) return;
        int4 a = reinterpret_cast<const int4*>(w)[2 * i];
        int4 b = reinterpret_cast<const int4*>(w)[2 * i + 1];
        __half h[8];
        h[0] = __int2half_rn(a.x); h[1] = __int2half_rn(a.y);
        h[2] = __int2half_rn(a.z); h[3] = __int2half_rn(a.w);
        h[4] = __int2half_rn(b.x); h[5] = __int2half_rn(b.y);
        h[6] = __int2half_rn(b.z); h[7] = __int2half_rn(b.w);
        reinterpret_cast<uint4*>(wh)[i] = *reinterpret_cast<uint4*>(h);
    } else {
        int i = (blockIdx.x - wblocks) * blockDim.x + threadIdx.x;
        float4 a = reinterpret_cast<const float4*>(x)[2 * i];
        float4 b = reinterpret_cast<const float4*>(x)[2 * i + 1];
        __half h[8];
        h[0] = __float2half_rn(a.x); h[1] = __float2half_rn(a.y);
        h[2] = __float2half_rn(a.z); h[3] = __float2half_rn(a.w);
        h[4] = __float2half_rn(b.x); h[5] = __float2half_rn(b.y);
        h[6] = __float2half_rn(b.z); h[7] = __float2half_rn(b.w);
        reinterpret_cast<uint4*>(xh)[i] = *reinterpret_cast<uint4*>(h);
    }
}

// ---------------------------------------------------------------------------
// PTX helpers
// ---------------------------------------------------------------------------
__device__ __forceinline__ uint32_t smem_u32(const void* p) {
    return (uint32_t)__cvta_generic_to_shared(p);
}

__device__ __forceinline__ uint32_t sw128(uint32_t off) {
    return off ^ ((off >> 3) & 0x70);
}

__device__ __forceinline__ void cp_async16(uint32_t s, const void* g) {
    asm volatile("cp.async.cg.shared.global [%0], [%1], 16;\n" ::"r"(s), "l"(g));
}

__device__ __forceinline__ void ldsm4(uint32_t r[4], uint32_t addr) {
    asm volatile("ldmatrix.sync.aligned.m8n8.x4.shared.b16 {%0,%1,%2,%3}, [%4];\n"
                 : "=r"(r[0]), "=r"(r[1]), "=r"(r[2]), "=r"(r[3])
                 : "r"(addr));
}

__device__ __forceinline__ void mma_16816(float c[4], const uint32_t a[4],
                                          const uint32_t b0, const uint32_t b1) {
    asm volatile(
        "mma.sync.aligned.m16n8k16.row.col.f32.f16.f16.f32 "
        "{%0,%1,%2,%3}, {%4,%5,%6,%7}, {%8,%9}, {%0,%1,%2,%3};\n"
        : "+f"(c[0]), "+f"(c[1]), "+f"(c[2]), "+f"(c[3])
        : "r"(a[0]), "r"(a[1]), "r"(a[2]), "r"(a[3]), "r"(b0), "r"(b1));
}

// ---------------------------------------------------------------------------
// Stage loader: A 128x64h + B 128x64h, XOR-128 swizzle
// ---------------------------------------------------------------------------
__device__ __forceinline__ void load_stage(uint32_t baseA, uint32_t baseB,
                                           const __half* __restrict__ Ag,
                                           const __half* __restrict__ Bg,
                                           int K, int k0, int tid) {
#pragma unroll
    for (int t = 0; t < 4; ++t) {
        int ch = tid + t * THREADS;   // 0..1023
        int row = ch >> 3;            // 0..127
        int c16 = ch & 7;             // 16B chunk in 128B row
        uint32_t sw = sw128((uint32_t)(row * 128 + c16 * 16));
        cp_async16(baseA + sw, Ag + (size_t)row * K + k0 + c16 * 8);
        cp_async16(baseB + sw, Bg + (size_t)row * K + k0 + c16 * 8);
    }
}

// ---------------------------------------------------------------------------
// GEMM (R6/R10 form; final iteration peeled)
// ---------------------------------------------------------------------------
__global__ void __launch_bounds__(THREADS, 2)
gemm_f16_kernel(const __half* __restrict__ A, const __half* __restrict__ Bw,
                const float* __restrict__ scale, float* __restrict__ C,
                int M, int N, int K) {
    extern __shared__ char smem[];
    const uint32_t sb = smem_u32(smem);

    const int tid = threadIdx.x;
    const int lane = tid & 31;
    const int warp = tid >> 5;
    const int warp_m = warp >> 2;  // 0..1 (64 rows)
    const int warp_n = warp & 3;   // 0..3 (32 cols)

    const int bm = blockIdx.x * BM;
    const int bn = blockIdx.y * BN;

    const __half* Ag = A + (size_t)bm * K;
    const __half* Bg = Bw + (size_t)bn * K;

    float acc[4][4][4];
#pragma unroll
    for (int i = 0; i < 4; ++i)
#pragma unroll
        for (int j = 0; j < 4; ++j)
#pragma unroll
            for (int v = 0; v < 4; ++v) acc[i][j][v] = 0.0f;

    const int KITERS = K / BK;  // 64

    // Prologue: stages 0,1
#pragma unroll
    for (int s = 0; s < STAGES - 1; ++s) {
        load_stage(sb + s * STAGE_BYTES, sb + s * STAGE_BYTES + 16384, Ag, Bg,
                   K, s * BK, tid);
        asm volatile("cp.async.commit_group;\n");
    }

    // Lane addressing (validated R5/R6)
    const uint32_t a_off0 =
        (uint32_t)((warp_m * 64 + (lane & 15)) * 128 + ((lane >> 4) << 4));
    const uint32_t b_off0 =
        (uint32_t)((warp_n * 32 + (lane & 7)) * 128 + ((lane >> 3) << 4));

    // Compute body for one landed stage
    auto compute_iter = [&](uint32_t Ast, uint32_t Bst) {
        uint32_t bf[4][2][4];
#pragma unroll
        for (int tn = 0; tn < 4; ++tn)
#pragma unroll
            for (int g = 0; g < 2; ++g)
                ldsm4(bf[tn][g], Bst + sw128(b_off0 + tn * 8 * 128 + g * 64));

#pragma unroll
        for (int ks = 0; ks < 4; ++ks) {
            uint32_t af[4][4];
#pragma unroll
            for (int tm = 0; tm < 4; ++tm)
                ldsm4(af[tm], Ast + sw128(a_off0 + tm * 16 * 128 + ks * 32));
            const int g = ks >> 1;
            const int p = (ks & 1) << 1;
#pragma unroll
            for (int tm = 0; tm < 4; ++tm)
#pragma unroll
                for (int tn = 0; tn < 4; ++tn)
                    mma_16816(acc[tm][tn], af[tm], bf[tn][g][p],
                              bf[tn][g][p + 1]);
        }
    };

    // Main loop: iterations 0 .. KITERS-2 (always prefetch-capable check only
    // on nxt; wait_group fixed at 1)
    for (int it = 0; it < KITERS - 1; ++it) {
        asm volatile("cp.async.wait_group 1;\n");
        __syncthreads();  // stage `it` visible; compute `it-1` finished by all

        int nxt = it + STAGES - 1;
        if (nxt < KITERS) {
            int ns = nxt % STAGES;
            load_stage(sb + ns * STAGE_BYTES, sb + ns * STAGE_BYTES + 16384,
                       Ag, Bg, K, nxt * BK, tid);
        }
        asm volatile("cp.async.commit_group;\n");

        const uint32_t Ast = sb + (it % STAGES) * STAGE_BYTES;
        compute_iter(Ast, Ast + 16384);
    }
    // Peeled final iteration: drain all pending groups, no prefetch
    {
        asm volatile("cp.async.wait_group 0;\n");
        __syncthreads();
        const uint32_t Ast = sb + ((KITERS - 1) % STAGES) * STAGE_BYTES;
        compute_iter(Ast, Ast + 16384);
    }

    // Epilogue: scale, round through f16, f32 pair stores
    const int c_row = lane >> 2;
    const int c_col = (lane & 3) << 1;

#pragma unroll
    for (int tm = 0; tm < 4; ++tm) {
#pragma unroll
        for (int tn = 0; tn < 4; ++tn) {
            int n = bn + warp_n * 32 + tn * 8 + c_col;
            float s0 = __ldg(scale + n);
            float s1 = __ldg(scale + n + 1);
            int m0 = bm + warp_m * 64 + tm * 16 + c_row;
            float2 r0, r1;
            r0.x = __half2float(__float2half_rn(acc[tm][tn][0] * s0));
            r0.y = __half2float(__float2half_rn(acc[tm][tn][1] * s1));
            r1.x = __half2float(__float2half_rn(acc[tm][tn][2] * s0));
            r1.y = __half2float(__float2half_rn(acc[tm][tn][3] * s1));
            *reinterpret_cast<float2*>(&C[(size_t)m0 * N + n]) = r0;
            *reinterpret_cast<float2*>(&C[(size_t)(m0 + 8) * N + n]) = r1;
        }
    }
}

// ---------------------------------------------------------------------------
// kernel_launch
// ---------------------------------------------------------------------------
extern "C" void kernel_launch(void* const* d_in, const int* in_sizes, int n_in,
                              void* d_out, int out_size) {
    const float* x = (const float*)d_in[0];
    const int* w32 = (const int*)d_in[1];  // int8 widened to int32
    const float* scale = (const float*)d_in[2];
    float* y = (float*)d_out;

    const int K = K_FIXED;
    const int N = in_sizes[2];      // 11008
    const int M = in_sizes[0] / K;  // 4096

    __half* wh = nullptr;
    cudaGetSymbolAddress((void**)&wh, g_wh);
    __half* xh = nullptr;
    cudaGetSymbolAddress((void**)&xh, g_xh);

    // Fused conversion: one launch covering W then x chunk ranges
    int nw8 = (N * K) / 8;                       // 5,636,096
    int nx8 = (M * K) / 8;                       // 2,097,152 (multiple of 256)
    int wblocks = (nw8 + 255) / 256;             // 22016
    int xblocks = nx8 / 256;                     // 8192
    convert_fused_kernel<<<wblocks + xblocks, 256>>>(w32, x, wh, xh, nw8,
                                                     wblocks);

    cudaFuncSetAttribute(gemm_f16_kernel,
                         cudaFuncAttributeMaxDynamicSharedMemorySize,
                         SMEM_TOTAL);

    dim3 grid(M / BM, N / BN);  // (32, 86); M fastest -> A L2-resident
    gemm_f16_kernel<<<grid, THREADS, SMEM_TOTAL>>>(xh, wh, scale, y, M, N, K);
}

// round 14
// speedup vs baseline: 1.1218x; 1.1218x over previous
#include <cuda_runtime.h>
#include <cuda_fp16.h>
#include <cstdint>

// ============================================================================
// Int8Linear: y[M,N] = (x[M,K] @ W^T[K,N]) * scale[n], fp32 accum
// M=4096, K=4096, N=11008.  compute_103 feature set (mma.sync + cp.async).
// FINAL (== R10/R12, session best: 898.1us, re-verified 898.8us).
// Pipeline: fused exact conversions (W int32->f16, x f32->f16) in one launch,
// then 128x128x64 mma.sync GEMM, 3-stage cp.async ring, XOR-128 swizzle,
// 2 CTAs/SM, one __syncthreads per K-iter, scale folded into epilogue with
// round-through-f16 to match reference .astype(float16).
// Plateau evidence: regfile 100% (127 regs x 512 thr/SM), tensor 71.7%,
// L1 61%, DRAM 4%; four controlled restructures (R7/R8/R11/R13) all
// regressed 60-160us -> this exact source is the ptxas-schedule optimum.
// ============================================================================

#define BM 128
#define BN 128
#define BK 64
#define STAGES 3
#define THREADS 256

#define STAGE_BYTES 32768  // A 16KB + B 16KB
#define SMEM_TOTAL (STAGES * STAGE_BYTES)  // 96 KB

#define N_MAX 11008
#define K_FIXED 4096
#define M_MAX 4096

__device__ __half g_wh[(size_t)N_MAX * K_FIXED];
__device__ __half g_xh[(size_t)M_MAX * K_FIXED];

// ---------------------------------------------------------------------------
// Fused conversion: blocks [0, wblocks) do W int32->f16 (exact, |w|<=127);
// blocks [wblocks, ...) do x f32->f16 (exact: values originally f16).
// ---------------------------------------------------------------------------
__global__ void convert_fused_kernel(const int* __restrict__ w,
                                     const float* __restrict__ x,
                                     __half* __restrict__ wh,
                                     __half* __restrict__ xh, int nw8,
                                     int wblocks) {
    if ((int)blockIdx.x < wblocks) {
        int i = blockIdx.x * blockDim.x + threadIdx.x;
        if (i >= nw8) return;
        int4 a = reinterpret_cast<const int4*>(w)[2 * i];
        int4 b = reinterpret_cast<const int4*>(w)[2 * i + 1];
        __half h[8];
        h[0] = __int2half_rn(a.x); h[1] = __int2half_rn(a.y);
        h[2] = __int2half_rn(a.z); h[3] = __int2half_rn(a.w);
        h[4] = __int2half_rn(b.x); h[5] = __int2half_rn(b.y);
        h[6] = __int2half_rn(b.z); h[7] = __int2half_rn(b.w);
        reinterpret_cast<uint4*>(wh)[i] = *reinterpret_cast<uint4*>(h);
    } else {
        int i = (blockIdx.x - wblocks) * blockDim.x + threadIdx.x;
        float4 a = reinterpret_cast<const float4*>(x)[2 * i];
        float4 b = reinterpret_cast<const float4*>(x)[2 * i + 1];
        __half h[8];
        h[0] = __float2half_rn(a.x); h[1] = __float2half_rn(a.y);
        h[2] = __float2half_rn(a.z); h[3] = __float2half_rn(a.w);
        h[4] = __float2half_rn(b.x); h[5] = __float2half_rn(b.y);
        h[6] = __float2half_rn(b.z); h[7] = __float2half_rn(b.w);
        reinterpret_cast<uint4*>(xh)[i] = *reinterpret_cast<uint4*>(h);
    }
}

// ---------------------------------------------------------------------------
// PTX helpers
// ---------------------------------------------------------------------------
__device__ __forceinline__ uint32_t smem_u32(const void* p) {
    return (uint32_t)__cvta_generic_to_shared(p);
}

__device__ __forceinline__ uint32_t sw128(uint32_t off) {
    return off ^ ((off >> 3) & 0x70);
}

__device__ __forceinline__ void cp_async16(uint32_t s, const void* g) {
    asm volatile("cp.async.cg.shared.global [%0], [%1], 16;\n" ::"r"(s), "l"(g));
}

__device__ __forceinline__ void ldsm4(uint32_t r[4], uint32_t addr) {
    asm volatile("ldmatrix.sync.aligned.m8n8.x4.shared.b16 {%0,%1,%2,%3}, [%4];\n"
                 : "=r"(r[0]), "=r"(r[1]), "=r"(r[2]), "=r"(r[3])
                 : "r"(addr));
}

__device__ __forceinline__ void mma_16816(float c[4], const uint32_t a[4],
                                          const uint32_t b0, const uint32_t b1) {
    asm volatile(
        "mma.sync.aligned.m16n8k16.row.col.f32.f16.f16.f32 "
        "{%0,%1,%2,%3}, {%4,%5,%6,%7}, {%8,%9}, {%0,%1,%2,%3};\n"
        : "+f"(c[0]), "+f"(c[1]), "+f"(c[2]), "+f"(c[3])
        : "r"(a[0]), "r"(a[1]), "r"(a[2]), "r"(a[3]), "r"(b0), "r"(b1));
}

// ---------------------------------------------------------------------------
// Stage loader: A 128x64h + B 128x64h, XOR-128 swizzle
// ---------------------------------------------------------------------------
__device__ __forceinline__ void load_stage(uint32_t baseA, uint32_t baseB,
                                           const __half* __restrict__ Ag,
                                           const __half* __restrict__ Bg,
                                           int K, int k0, int tid) {
#pragma unroll
    for (int t = 0; t < 4; ++t) {
        int ch = tid + t * THREADS;   // 0..1023
        int row = ch >> 3;            // 0..127
        int c16 = ch & 7;             // 16B chunk in 128B row
        uint32_t sw = sw128((uint32_t)(row * 128 + c16 * 16));
        cp_async16(baseA + sw, Ag + (size_t)row * K + k0 + c16 * 8);
        cp_async16(baseB + sw, Bg + (size_t)row * K + k0 + c16 * 8);
    }
}

// ---------------------------------------------------------------------------
// GEMM (R6/R10 form — measured best: GEMM 849-852 us, tensor 71.7%)
// ---------------------------------------------------------------------------
__global__ void __launch_bounds__(THREADS, 2)
gemm_f16_kernel(const __half* __restrict__ A, const __half* __restrict__ Bw,
                const float* __restrict__ scale, float* __restrict__ C,
                int M, int N, int K) {
    extern __shared__ char smem[];
    const uint32_t sb = smem_u32(smem);

    const int tid = threadIdx.x;
    const int lane = tid & 31;
    const int warp = tid >> 5;
    const int warp_m = warp >> 2;  // 0..1 (64 rows)
    const int warp_n = warp & 3;   // 0..3 (32 cols)

    const int bm = blockIdx.x * BM;
    const int bn = blockIdx.y * BN;

    const __half* Ag = A + (size_t)bm * K;
    const __half* Bg = Bw + (size_t)bn * K;

    float acc[4][4][4];
#pragma unroll
    for (int i = 0; i < 4; ++i)
#pragma unroll
        for (int j = 0; j < 4; ++j)
#pragma unroll
            for (int v = 0; v < 4; ++v) acc[i][j][v] = 0.0f;

    const int KITERS = K / BK;  // 64

    // Prologue: stages 0,1
#pragma unroll
    for (int s = 0; s < STAGES - 1; ++s) {
        load_stage(sb + s * STAGE_BYTES, sb + s * STAGE_BYTES + 16384, Ag, Bg,
                   K, s * BK, tid);
        asm volatile("cp.async.commit_group;\n");
    }

    // Lane addressing (validated R5/R6)
    const uint32_t a_off0 =
        (uint32_t)((warp_m * 64 + (lane & 15)) * 128 + ((lane >> 4) << 4));
    const uint32_t b_off0 =
        (uint32_t)((warp_n * 32 + (lane & 7)) * 128 + ((lane >> 3) << 4));

    for (int it = 0; it < KITERS; ++it) {
        if (it + 1 < KITERS) {
            asm volatile("cp.async.wait_group 1;\n");
        } else {
            asm volatile("cp.async.wait_group 0;\n");
        }
        __syncthreads();  // stage `it` visible; compute `it-1` finished by all

        // Prefetch stage it+2 into the slot consumed at it-1 (safe post-sync)
        int nxt = it + STAGES - 1;
        if (nxt < KITERS) {
            int ns = nxt % STAGES;
            load_stage(sb + ns * STAGE_BYTES, sb + ns * STAGE_BYTES + 16384,
                       Ag, Bg, K, nxt * BK, tid);
        }
        asm volatile("cp.async.commit_group;\n");

        const uint32_t Ast = sb + (it % STAGES) * STAGE_BYTES;
        const uint32_t Bst = Ast + 16384;

        // Hoist ALL B fragments for this iteration: tn x {k0-31, k32-63}
        uint32_t bf[4][2][4];
#pragma unroll
        for (int tn = 0; tn < 4; ++tn)
#pragma unroll
            for (int g = 0; g < 2; ++g)
                ldsm4(bf[tn][g], Bst + sw128(b_off0 + tn * 8 * 128 + g * 64));

#pragma unroll
        for (int ks = 0; ks < 4; ++ks) {
            uint32_t af[4][4];
#pragma unroll
            for (int tm = 0; tm < 4; ++tm)
                ldsm4(af[tm], Ast + sw128(a_off0 + tm * 16 * 128 + ks * 32));
            const int g = ks >> 1;
            const int p = (ks & 1) << 1;
#pragma unroll
            for (int tm = 0; tm < 4; ++tm)
#pragma unroll
                for (int tn = 0; tn < 4; ++tn)
                    mma_16816(acc[tm][tn], af[tm], bf[tn][g][p],
                              bf[tn][g][p + 1]);
        }
    }

    // Epilogue: scale, round through f16, f32 pair stores
    const int c_row = lane >> 2;
    const int c_col = (lane & 3) << 1;

#pragma unroll
    for (int tm = 0; tm < 4; ++tm) {
#pragma unroll
        for (int tn = 0; tn < 4; ++tn) {
            int n = bn + warp_n * 32 + tn * 8 + c_col;
            float s0 = __ldg(scale + n);
            float s1 = __ldg(scale + n + 1);
            int m0 = bm + warp_m * 64 + tm * 16 + c_row;
            float2 r0, r1;
            r0.x = __half2float(__float2half_rn(acc[tm][tn][0] * s0));
            r0.y = __half2float(__float2half_rn(acc[tm][tn][1] * s1));
            r1.x = __half2float(__float2half_rn(acc[tm][tn][2] * s0));
            r1.y = __half2float(__float2half_rn(acc[tm][tn][3] * s1));
            *reinterpret_cast<float2*>(&C[(size_t)m0 * N + n]) = r0;
            *reinterpret_cast<float2*>(&C[(size_t)(m0 + 8) * N + n]) = r1;
        }
    }
}

// ---------------------------------------------------------------------------
// kernel_launch
// ---------------------------------------------------------------------------
extern "C" void kernel_launch(void* const* d_in, const int* in_sizes, int n_in,
                              void* d_out, int out_size) {
    const float* x = (const float*)d_in[0];
    const int* w32 = (const int*)d_in[1];  // int8 widened to int32
    const float* scale = (const float*)d_in[2];
    float* y = (float*)d_out;

    const int K = K_FIXED;
    const int N = in_sizes[2];      // 11008
    const int M = in_sizes[0] / K;  // 4096

    __half* wh = nullptr;
    cudaGetSymbolAddress((void**)&wh, g_wh);
    __half* xh = nullptr;
    cudaGetSymbolAddress((void**)&xh, g_xh);

    // Fused conversion: one launch covering W then x chunk ranges
    int nw8 = (N * K) / 8;                       // 5,636,096
    int nx8 = (M * K) / 8;                       // 2,097,152 (multiple of 256)
    int wblocks = (nw8 + 255) / 256;             // 22016
    int xblocks = nx8 / 256;                     // 8192
    convert_fused_kernel<<<wblocks + xblocks, 256>>>(w32, x, wh, xh, nw8,
                                                     wblocks);

    cudaFuncSetAttribute(gemm_f16_kernel,
                         cudaFuncAttributeMaxDynamicSharedMemorySize,
                         SMEM_TOTAL);

    dim3 grid(M / BM, N / BN);  // (32, 86); M fastest -> A L2-resident
    gemm_f16_kernel<<<grid, THREADS, SMEM_TOTAL>>>(xh, wh, scale, y, M, N, K);
}